// round 1
// baseline (speedup 1.0000x reference)
#include <cuda_runtime.h>

#define B_ 256
#define L_ 4096
#define H_ 64
#define V_ 64

// Scratch (allocation-free rule: __device__ globals)
__device__ float g_K[V_ * H_];    // LN(embed + FF(embed)) per vocab id
__device__ float g_invd[V_];      // 1 / (||k||^2 + 1e-6)

// ---------------------------------------------------------------------------
// Phase 1: build the 64x64 token table. h[b,l] depends only on seq[b,l] since
// vocab == 64, so embed+FF+LN collapses to a per-vocab row.
// grid 64 blocks (one per vocab id) x 64 threads.
// ---------------------------------------------------------------------------
__global__ void build_table_kernel(const float* __restrict__ embed_W,
                                   const float* __restrict__ w1,
                                   const float* __restrict__ b1,
                                   const float* __restrict__ w2,
                                   const float* __restrict__ b2,
                                   const float* __restrict__ lnw,
                                   const float* __restrict__ lnb)
{
    __shared__ float e[H_];
    __shared__ float a[2 * H_];
    __shared__ float hrow[H_];
    __shared__ float red[H_];

    const int v = blockIdx.x;
    const int t = threadIdx.x;

    e[t] = embed_W[v * H_ + t];
    __syncthreads();

    // ff1 + relu : thread t computes outputs t and t+64
    float acc0 = b1[t], acc1 = b1[t + H_];
    #pragma unroll 8
    for (int k = 0; k < H_; k++) {
        float ek = e[k];
        acc0 += ek * w1[k * (2 * H_) + t];
        acc1 += ek * w1[k * (2 * H_) + t + H_];
    }
    a[t]      = fmaxf(acc0, 0.f);
    a[t + H_] = fmaxf(acc1, 0.f);
    __syncthreads();

    // ff2 + residual
    float f = b2[t];
    #pragma unroll 8
    for (int o = 0; o < 2 * H_; o++) f += a[o] * w2[o * H_ + t];
    hrow[t] = e[t] + f;
    __syncthreads();

    // layer norm (redundant per-thread reduction over 64 elems -> broadcast LDS)
    float mu = 0.f;
    #pragma unroll 8
    for (int j = 0; j < H_; j++) mu += hrow[j];
    mu *= (1.f / H_);
    float var = 0.f;
    #pragma unroll 8
    for (int j = 0; j < H_; j++) { float d = hrow[j] - mu; var += d * d; }
    var *= (1.f / H_);

    float kv = (hrow[t] - mu) * rsqrtf(var + 1e-5f) * lnw[t] + lnb[t];
    g_K[v * H_ + t] = kv;

    red[t] = kv * kv;
    __syncthreads();
    if (t == 0) {
        float d = 0.f;
        #pragma unroll 8
        for (int j = 0; j < H_; j++) d += red[j];
        g_invd[v] = 1.f / (d + 1e-6f);
    }
}

// ---------------------------------------------------------------------------
// Phase 2+3: delta-rule scan + readout.
// Block = 128 threads = 2 batches (64 threads each) -> warps land one per
// SMSP. Thread i owns row M[i,:] in 64 registers. k rows are broadcast LDS
// reads from the shared table; no per-step synchronization needed.
// grid = 128 blocks (256 batches / 2).
// ---------------------------------------------------------------------------
__global__ __launch_bounds__(128, 1)
void scan_kernel(const int* __restrict__ seq,
                 const float* __restrict__ read_w,
                 const float* __restrict__ read_b,
                 const float* __restrict__ out_w,
                 const float* __restrict__ out_b,
                 float* __restrict__ out)
{
    __shared__ float Ksh[V_ * H_];
    __shared__ float invd_sh[V_];
    __shared__ float xch[2][H_];

    // cooperative load of table into shared
    for (int idx = threadIdx.x; idx < (V_ * H_) / 4; idx += blockDim.x)
        reinterpret_cast<float4*>(Ksh)[idx] =
            reinterpret_cast<const float4*>(g_K)[idx];
    if (threadIdx.x < V_) invd_sh[threadIdx.x] = g_invd[threadIdx.x];
    __syncthreads();

    const int half = threadIdx.x >> 6;   // which batch inside the block
    const int i    = threadIdx.x & 63;   // row of M owned by this thread
    const int b    = blockIdx.x * 2 + half;
    const int* sp  = seq + (long)b * L_;

    float M[H_];
    #pragma unroll
    for (int j = 0; j < H_; j++) M[j] = 0.f;

    int s = __ldg(sp);
    #pragma unroll 1
    for (int t = 0; t < L_ - 1; t++) {
        const int snext = __ldg(sp + t + 1);   // prefetch next token id

        const float4* krow = reinterpret_cast<const float4*>(Ksh + s * H_);
        float4 kq[16];
        #pragma unroll
        for (int u = 0; u < 16; u++) kq[u] = krow[u];

        const float id = invd_sh[s];
        const float ki = Ksh[s * H_ + i];

        // v_pred[i] = M[i,:] . k   (4 independent accumulator chains)
        float a0 = 0.f, a1 = 0.f, a2 = 0.f, a3 = 0.f;
        #pragma unroll
        for (int u = 0; u < 16; u++) {
            a0 += M[4 * u + 0] * kq[u].x;
            a1 += M[4 * u + 1] * kq[u].y;
            a2 += M[4 * u + 2] * kq[u].z;
            a3 += M[4 * u + 3] * kq[u].w;
        }
        const float vp = (a0 + a1) + (a2 + a3);
        const float dv = ki - vp * id;

        // rank-1 update of the owned row
        #pragma unroll
        for (int u = 0; u < 16; u++) {
            M[4 * u + 0] += dv * kq[u].x;
            M[4 * u + 1] += dv * kq[u].y;
            M[4 * u + 2] += dv * kq[u].z;
            M[4 * u + 3] += dv * kq[u].w;
        }
        s = snext;
    }

    // s now holds seq[b, L-1]  ->  ctx = M @ q
    {
        const float4* krow = reinterpret_cast<const float4*>(Ksh + s * H_);
        float a0 = 0.f, a1 = 0.f, a2 = 0.f, a3 = 0.f;
        #pragma unroll
        for (int u = 0; u < 16; u++) {
            const float4 kv = krow[u];
            a0 += M[4 * u + 0] * kv.x;
            a1 += M[4 * u + 1] * kv.y;
            a2 += M[4 * u + 2] * kv.z;
            a3 += M[4 * u + 3] * kv.w;
        }
        xch[half][i] = (a0 + a1) + (a2 + a3);
    }
    __syncthreads();

    // r = ctx @ read_w + read_b
    float r = read_b[i];
    #pragma unroll 8
    for (int j = 0; j < H_; j++) r += xch[half][j] * read_w[j * H_ + i];
    __syncthreads();
    xch[half][i] = r;
    __syncthreads();

    // out = r @ out_w + out_b
    float o = out_b[i];
    #pragma unroll 8
    for (int j = 0; j < H_; j++) o += xch[half][j] * out_w[j * V_ + i];
    out[b * V_ + i] = o;
}

// ---------------------------------------------------------------------------
extern "C" void kernel_launch(void* const* d_in, const int* in_sizes, int n_in,
                              void* d_out, int out_size)
{
    const int*   seq     = (const int*)  d_in[0];
    const float* embed_W = (const float*)d_in[1];
    const float* ff_w1   = (const float*)d_in[2];
    const float* ff_b1   = (const float*)d_in[3];
    const float* ff_w2   = (const float*)d_in[4];
    const float* ff_b2   = (const float*)d_in[5];
    const float* ln_w    = (const float*)d_in[6];
    const float* ln_b    = (const float*)d_in[7];
    const float* read_w  = (const float*)d_in[8];
    const float* read_b  = (const float*)d_in[9];
    const float* out_w   = (const float*)d_in[10];
    const float* out_b   = (const float*)d_in[11];
    float* out = (float*)d_out;

    build_table_kernel<<<V_, H_>>>(embed_W, ff_w1, ff_b1, ff_w2, ff_b2,
                                   ln_w, ln_b);
    scan_kernel<<<B_ / 2, 128>>>(seq, read_w, read_b, out_w, out_b, out);
}

// round 2
// speedup vs baseline: 1.0126x; 1.0126x over previous
#include <cuda_runtime.h>

#define B_ 256
#define L_ 4096
#define H_ 64
#define V_ 64

// Scratch (allocation-free rule: __device__ globals)
__device__ float g_K[V_ * H_];    // LN(embed + FF(embed)) per vocab id
__device__ float g_invd[V_];      // 1 / (||k||^2 + 1e-6)

// ---------------------------------------------------------------------------
// Packed f32x2 helpers (Blackwell FFMA2 — only reachable via PTX)
// ---------------------------------------------------------------------------
__device__ __forceinline__ unsigned long long ffma2(unsigned long long a,
                                                    unsigned long long b,
                                                    unsigned long long c)
{
    unsigned long long d;
    asm("fma.rn.f32x2 %0, %1, %2, %3;" : "=l"(d) : "l"(a), "l"(b), "l"(c));
    return d;
}

__device__ __forceinline__ unsigned long long pack2(float x)
{
    unsigned long long d;
    asm("mov.b64 %0, {%1, %1};" : "=l"(d) : "f"(x));
    return d;
}

__device__ __forceinline__ void unpack2(unsigned long long p, float& lo, float& hi)
{
    asm("mov.b64 {%0, %1}, %2;" : "=f"(lo), "=f"(hi) : "l"(p));
}

// ---------------------------------------------------------------------------
// Phase 1: build the 64x64 token table. h[b,l] depends only on seq[b,l] since
// vocab == 64, so embed+FF+LN collapses to a per-vocab row.
// ---------------------------------------------------------------------------
__global__ void build_table_kernel(const float* __restrict__ embed_W,
                                   const float* __restrict__ w1,
                                   const float* __restrict__ b1,
                                   const float* __restrict__ w2,
                                   const float* __restrict__ b2,
                                   const float* __restrict__ lnw,
                                   const float* __restrict__ lnb)
{
    __shared__ float e[H_];
    __shared__ float a[2 * H_];
    __shared__ float hrow[H_];
    __shared__ float red[H_];

    const int v = blockIdx.x;
    const int t = threadIdx.x;

    e[t] = embed_W[v * H_ + t];
    __syncthreads();

    float acc0 = b1[t], acc1 = b1[t + H_];
    #pragma unroll 8
    for (int k = 0; k < H_; k++) {
        float ek = e[k];
        acc0 += ek * w1[k * (2 * H_) + t];
        acc1 += ek * w1[k * (2 * H_) + t + H_];
    }
    a[t]      = fmaxf(acc0, 0.f);
    a[t + H_] = fmaxf(acc1, 0.f);
    __syncthreads();

    float f = b2[t];
    #pragma unroll 8
    for (int o = 0; o < 2 * H_; o++) f += a[o] * w2[o * H_ + t];
    hrow[t] = e[t] + f;
    __syncthreads();

    float mu = 0.f;
    #pragma unroll 8
    for (int j = 0; j < H_; j++) mu += hrow[j];
    mu *= (1.f / H_);
    float var = 0.f;
    #pragma unroll 8
    for (int j = 0; j < H_; j++) { float d = hrow[j] - mu; var += d * d; }
    var *= (1.f / H_);

    float kv = (hrow[t] - mu) * rsqrtf(var + 1e-5f) * lnw[t] + lnb[t];
    g_K[v * H_ + t] = kv;

    red[t] = kv * kv;
    __syncthreads();
    if (t == 0) {
        float d = 0.f;
        #pragma unroll 8
        for (int j = 0; j < H_; j++) d += red[j];
        g_invd[v] = 1.f / (d + 1e-6f);
    }
}

// ---------------------------------------------------------------------------
// Scan helpers
// ---------------------------------------------------------------------------
__device__ __forceinline__ void loadrow(ulonglong2 kb[16], const float* Ksh, int s)
{
    const ulonglong2* r = reinterpret_cast<const ulonglong2*>(Ksh + s * H_);
    #pragma unroll
    for (int u = 0; u < 16; u++) kb[u] = r[u];
}

// One delta-rule step on the thread-owned packed row Mp (32 x f32x2 = 64 fp32).
__device__ __forceinline__ void scan_step(unsigned long long Mp[32],
                                          const ulonglong2 kb[16],
                                          float ki, float id)
{
    unsigned long long p0 = 0ull, p1 = 0ull;
    #pragma unroll
    for (int u = 0; u < 16; u++) {
        p0 = ffma2(Mp[2 * u],     kb[u].x, p0);
        p1 = ffma2(Mp[2 * u + 1], kb[u].y, p1);
    }
    float l0, h0, l1, h1;
    unpack2(p0, l0, h0);
    unpack2(p1, l1, h1);
    const float vp = (l0 + h0) + (l1 + h1);
    const float dv = ki - vp * id;
    const unsigned long long dvp = pack2(dv);
    #pragma unroll
    for (int u = 0; u < 16; u++) {
        Mp[2 * u]     = ffma2(dvp, kb[u].x, Mp[2 * u]);
        Mp[2 * u + 1] = ffma2(dvp, kb[u].y, Mp[2 * u + 1]);
    }
}

__device__ __forceinline__ float dotrow(const unsigned long long Mp[32],
                                        const ulonglong2 kb[16])
{
    unsigned long long p0 = 0ull, p1 = 0ull;
    #pragma unroll
    for (int u = 0; u < 16; u++) {
        p0 = ffma2(Mp[2 * u],     kb[u].x, p0);
        p1 = ffma2(Mp[2 * u + 1], kb[u].y, p1);
    }
    float l0, h0, l1, h1;
    unpack2(p0, l0, h0);
    unpack2(p1, l1, h1);
    return (l0 + h0) + (l1 + h1);
}

// ---------------------------------------------------------------------------
// Phase 2+3: delta-rule scan + readout.
// Block = 128 threads = 2 batches (64 each); thread i owns row M[i,:] packed
// into 32 f32x2 registers. k rows broadcast from shared; double-buffered
// software pipeline hides LDS latency.
// ---------------------------------------------------------------------------
__global__ __launch_bounds__(128, 1)
void scan_kernel(const int* __restrict__ seq,
                 const float* __restrict__ read_w,
                 const float* __restrict__ read_b,
                 const float* __restrict__ out_w,
                 const float* __restrict__ out_b,
                 float* __restrict__ out)
{
    __shared__ float Ksh[V_ * H_];
    __shared__ float invd_sh[V_];
    __shared__ float xch[2][H_];

    for (int idx = threadIdx.x; idx < (V_ * H_) / 4; idx += blockDim.x)
        reinterpret_cast<float4*>(Ksh)[idx] =
            reinterpret_cast<const float4*>(g_K)[idx];
    if (threadIdx.x < V_) invd_sh[threadIdx.x] = g_invd[threadIdx.x];
    __syncthreads();

    const int half = threadIdx.x >> 6;
    const int i    = threadIdx.x & 63;
    const int b    = blockIdx.x * 2 + half;
    const int* sp  = seq + (long)b * L_;

    unsigned long long Mp[32];
    #pragma unroll
    for (int j = 0; j < 32; j++) Mp[j] = 0ull;

    ulonglong2 bufA[16], bufB[16];

    int s0 = __ldg(sp + 0);   // token for step t
    int s1 = __ldg(sp + 1);   // token for step t+1
    loadrow(bufA, Ksh, s0);

    // steps 0..L-3 in pairs (L_-1 = 4095 total scan steps; last one after loop)
    #pragma unroll 1
    for (int t = 0; t < L_ - 2; t += 2) {
        loadrow(bufB, Ksh, s1);                 // prefetch k for step t+1
        const int s2 = __ldg(sp + t + 2);
        {
            const float ki = Ksh[s0 * H_ + i];
            const float id = invd_sh[s0];
            scan_step(Mp, bufA, ki, id);        // step t
        }
        loadrow(bufA, Ksh, s2);                 // prefetch k for step t+2
        const int s3 = __ldg(sp + t + 3);       // in-bounds: t+3 <= 4095
        {
            const float ki = Ksh[s1 * H_ + i];
            const float id = invd_sh[s1];
            scan_step(Mp, bufB, ki, id);        // step t+1
        }
        s0 = s2;
        s1 = s3;
    }
    // s0 = seq[L-2] (last scan step, k already in bufA), s1 = seq[L-1] (query)
    scan_step(Mp, bufA, Ksh[s0 * H_ + i], invd_sh[s0]);

    // ctx = M @ q  (q = table row of the final token)
    loadrow(bufB, Ksh, s1);
    xch[half][i] = dotrow(Mp, bufB);
    __syncthreads();

    // r = ctx @ read_w + read_b
    float r = read_b[i];
    #pragma unroll 8
    for (int j = 0; j < H_; j++) r += xch[half][j] * read_w[j * H_ + i];
    __syncthreads();
    xch[half][i] = r;
    __syncthreads();

    // out = r @ out_w + out_b
    float o = out_b[i];
    #pragma unroll 8
    for (int j = 0; j < H_; j++) o += xch[half][j] * out_w[j * V_ + i];
    out[b * V_ + i] = o;
}

// ---------------------------------------------------------------------------
extern "C" void kernel_launch(void* const* d_in, const int* in_sizes, int n_in,
                              void* d_out, int out_size)
{
    const int*   seq     = (const int*)  d_in[0];
    const float* embed_W = (const float*)d_in[1];
    const float* ff_w1   = (const float*)d_in[2];
    const float* ff_b1   = (const float*)d_in[3];
    const float* ff_w2   = (const float*)d_in[4];
    const float* ff_b2   = (const float*)d_in[5];
    const float* ln_w    = (const float*)d_in[6];
    const float* ln_b    = (const float*)d_in[7];
    const float* read_w  = (const float*)d_in[8];
    const float* read_b  = (const float*)d_in[9];
    const float* out_w   = (const float*)d_in[10];
    const float* out_b   = (const float*)d_in[11];
    float* out = (float*)d_out;

    build_table_kernel<<<V_, H_>>>(embed_W, ff_w1, ff_b1, ff_w2, ff_b2,
                                   ln_w, ln_b);
    scan_kernel<<<B_ / 2, 128>>>(seq, read_w, read_b, out_w, out_b, out);
}

// round 3
// speedup vs baseline: 1.2272x; 1.2119x over previous
#include <cuda_runtime.h>

#define B_ 256
#define L_ 4096
#define H_ 64
#define V_ 64

// Scratch (allocation-free rule: __device__ globals)
__device__ float g_K[V_ * H_];    // LN(embed + FF(embed)) per vocab id
__device__ float g_invd[V_];      // 1 / (||k||^2 + 1e-6)
__device__ float g_G[V_ * V_];    // Gram: G[a][b] = k_a . k_b

// ---------------------------------------------------------------------------
// Phase 1a: build the 64x64 token table (vocab == 64 collapses embed+FF+LN).
// ---------------------------------------------------------------------------
__global__ void build_table_kernel(const float* __restrict__ embed_W,
                                   const float* __restrict__ w1,
                                   const float* __restrict__ b1,
                                   const float* __restrict__ w2,
                                   const float* __restrict__ b2,
                                   const float* __restrict__ lnw,
                                   const float* __restrict__ lnb)
{
    __shared__ float e[H_];
    __shared__ float a[2 * H_];
    __shared__ float hrow[H_];
    __shared__ float red[H_];

    const int v = blockIdx.x;
    const int t = threadIdx.x;

    e[t] = embed_W[v * H_ + t];
    __syncthreads();

    float acc0 = b1[t], acc1 = b1[t + H_];
    #pragma unroll 8
    for (int k = 0; k < H_; k++) {
        float ek = e[k];
        acc0 += ek * w1[k * (2 * H_) + t];
        acc1 += ek * w1[k * (2 * H_) + t + H_];
    }
    a[t]      = fmaxf(acc0, 0.f);
    a[t + H_] = fmaxf(acc1, 0.f);
    __syncthreads();

    float f = b2[t];
    #pragma unroll 8
    for (int o = 0; o < 2 * H_; o++) f += a[o] * w2[o * H_ + t];
    hrow[t] = e[t] + f;
    __syncthreads();

    float mu = 0.f;
    #pragma unroll 8
    for (int j = 0; j < H_; j++) mu += hrow[j];
    mu *= (1.f / H_);
    float var = 0.f;
    #pragma unroll 8
    for (int j = 0; j < H_; j++) { float d = hrow[j] - mu; var += d * d; }
    var *= (1.f / H_);

    float kv = (hrow[t] - mu) * rsqrtf(var + 1e-5f) * lnw[t] + lnb[t];
    g_K[v * H_ + t] = kv;

    red[t] = kv * kv;
    __syncthreads();
    if (t == 0) {
        float d = 0.f;
        #pragma unroll 8
        for (int j = 0; j < H_; j++) d += red[j];
        g_invd[v] = 1.f / (d + 1e-6f);
    }
}

// ---------------------------------------------------------------------------
// Phase 1b: Gram matrix G = K K^T  (64x64). grid 64 x block 64.
// ---------------------------------------------------------------------------
__global__ void build_gram_kernel()
{
    __shared__ float Kt[V_ * H_];
    const int t = threadIdx.x;
    for (int idx = t; idx < V_ * H_ / 4; idx += H_)
        reinterpret_cast<float4*>(Kt)[idx] = reinterpret_cast<const float4*>(g_K)[idx];
    __syncthreads();

    const int arow = blockIdx.x;
    float acc = 0.f;
    #pragma unroll 8
    for (int i = 0; i < H_; i++)
        acc += Kt[arow * H_ + i] * Kt[t * H_ + i];
    g_G[arow * V_ + t] = acc;
}

// ---------------------------------------------------------------------------
// Chunk worker: T steps of the coefficient-space delta recurrence.
// C (64 regs) = column `tid` of the 64x128 C matrix (two batches per block).
// Csnap: shared [64][128]; each thread writes/reads only its own column, so
// no synchronization is needed.
// ---------------------------------------------------------------------------
template<int T>
__device__ __forceinline__ void do_chunk(float C[H_],
                                         const int s[16],
                                         const float* __restrict__ G_sh,
                                         const float* __restrict__ invd_sh,
                                         float* __restrict__ Csnap,
                                         int tid, int hw64)
{
    // snapshot own column
    #pragma unroll
    for (int x = 0; x < H_; x++) Csnap[x * 128 + tid] = C[x];

    // gather the T rows this chunk will need (start-of-chunk values)
    float bv[T];
    #pragma unroll
    for (int j = 0; j < T; j++) bv[j] = Csnap[(s[j] << 7) + tid];

    float alpha[T];
    #pragma unroll
    for (int j = 0; j < T; j++) {
        // beta = C_t[s_j][tid] = snapshot + within-chunk corrections
        float b0 = bv[j], b1 = 0.f;
        #pragma unroll
        for (int u = 0; u < j; u++) {
            const float gv = G_sh[(s[u] << 6) + s[j]];
            if (u & 1) b1 = fmaf(gv, alpha[u], b1);
            else       b0 = fmaf(gv, alpha[u], b0);
        }
        const float beta = b0 + b1;
        const float e = (hw64 == s[j]) ? 1.f : 0.f;
        const float a = fmaf(-invd_sh[s[j]], beta, e);
        alpha[j] = a;

        // rank-1 update: C[x] += G[s_j][x] * a
        const float4* g = reinterpret_cast<const float4*>(G_sh + (s[j] << 6));
        #pragma unroll
        for (int u = 0; u < 16; u++) {
            const float4 gq = g[u];
            C[4 * u + 0] = fmaf(gq.x, a, C[4 * u + 0]);
            C[4 * u + 1] = fmaf(gq.y, a, C[4 * u + 1]);
            C[4 * u + 2] = fmaf(gq.z, a, C[4 * u + 2]);
            C[4 * u + 3] = fmaf(gq.w, a, C[4 * u + 3]);
        }
    }
}

// ---------------------------------------------------------------------------
// Phase 2+3: coefficient-space scan + readout.
// Block = 128 threads = 2 batches (64 columns each). grid = 128.
// Dynamic shared: G (16KB) | Csnap 64x128 (32KB) | invd (256B) | xch (512B)
// ---------------------------------------------------------------------------
extern __shared__ float s_dyn[];

__global__ __launch_bounds__(128, 1)
void scan_kernel(const int* __restrict__ seq,
                 const float* __restrict__ read_w,
                 const float* __restrict__ read_b,
                 const float* __restrict__ out_w,
                 const float* __restrict__ out_b,
                 float* __restrict__ out)
{
    float* G_sh    = s_dyn;                 // 4096 floats
    float* Csnap   = s_dyn + 4096;          // 8192 floats
    float* invd_sh = s_dyn + 4096 + 8192;   // 64
    float* xch     = invd_sh + 64;          // 128

    const int tid  = threadIdx.x;
    const int half = tid >> 6;
    const int hw64 = tid & 63;
    const int bb   = blockIdx.x * 2 + half;

    for (int idx = tid; idx < (V_ * V_) / 4; idx += 128)
        reinterpret_cast<float4*>(G_sh)[idx] = reinterpret_cast<const float4*>(g_G)[idx];
    if (tid < V_) invd_sh[tid] = g_invd[tid];
    __syncthreads();

    float C[H_];
    #pragma unroll
    for (int x = 0; x < H_; x++) C[x] = 0.f;

    const int4* sp4 = reinterpret_cast<const int4*>(seq + (long)bb * L_);

    // prefetch chunk 0 tokens (16 ints = 4 x int4, uniform per half)
    int4 p0 = __ldg(sp4 + 0), p1 = __ldg(sp4 + 1),
         p2 = __ldg(sp4 + 2), p3 = __ldg(sp4 + 3);

    // 255 full chunks of 16 steps (t = 0..4079); no block syncs inside.
    #pragma unroll 1
    for (int c = 0; c < 255; c++) {
        const int s[16] = { p0.x, p0.y, p0.z, p0.w,  p1.x, p1.y, p1.z, p1.w,
                            p2.x, p2.y, p2.z, p2.w,  p3.x, p3.y, p3.z, p3.w };
        const int nb = (c + 1) * 4;            // next chunk, in int4 units
        p0 = __ldg(sp4 + nb + 0);
        p1 = __ldg(sp4 + nb + 1);
        p2 = __ldg(sp4 + nb + 2);
        p3 = __ldg(sp4 + nb + 3);

        do_chunk<16>(C, s, G_sh, invd_sh, Csnap, tid, hw64);
    }

    // tail: t = 4080..4094 (15 steps); s[15] = seq[4095] is the query token.
    const int s[16] = { p0.x, p0.y, p0.z, p0.w,  p1.x, p1.y, p1.z, p1.w,
                        p2.x, p2.y, p2.z, p2.w,  p3.x, p3.y, p3.z, p3.w };
    do_chunk<15>(C, s, G_sh, invd_sh, Csnap, tid, hw64);
    const int sq = s[15];

    // ctx = K^T C_final[sq,:]  — final snapshot + own-column gather
    #pragma unroll
    for (int x = 0; x < H_; x++) Csnap[x * 128 + tid] = C[x];
    const float Aw = Csnap[(sq << 7) + tid];

    xch[tid] = Aw;
    __syncthreads();
    float ctx = 0.f;
    #pragma unroll 8
    for (int w = 0; w < H_; w++)
        ctx = fmaf(xch[half * 64 + w], __ldg(g_K + w * H_ + hw64), ctx);
    __syncthreads();
    xch[tid] = ctx;
    __syncthreads();

    float r = read_b[hw64];
    #pragma unroll 8
    for (int j = 0; j < H_; j++) r = fmaf(xch[half * 64 + j], read_w[j * H_ + hw64], r);
    __syncthreads();
    xch[tid] = r;
    __syncthreads();

    float o = out_b[hw64];
    #pragma unroll 8
    for (int j = 0; j < H_; j++) o = fmaf(xch[half * 64 + j], out_w[j * V_ + hw64], o);
    out[bb * V_ + hw64] = o;
}

// ---------------------------------------------------------------------------
extern "C" void kernel_launch(void* const* d_in, const int* in_sizes, int n_in,
                              void* d_out, int out_size)
{
    const int*   seq     = (const int*)  d_in[0];
    const float* embed_W = (const float*)d_in[1];
    const float* ff_w1   = (const float*)d_in[2];
    const float* ff_b1   = (const float*)d_in[3];
    const float* ff_w2   = (const float*)d_in[4];
    const float* ff_b2   = (const float*)d_in[5];
    const float* ln_w    = (const float*)d_in[6];
    const float* ln_b    = (const float*)d_in[7];
    const float* read_w  = (const float*)d_in[8];
    const float* read_b  = (const float*)d_in[9];
    const float* out_w   = (const float*)d_in[10];
    const float* out_b   = (const float*)d_in[11];
    float* out = (float*)d_out;

    const int smem_bytes = (4096 + 8192 + 64 + 128) * 4;   // 49920 B
    static int attr_done = 0;
    cudaFuncSetAttribute(scan_kernel,
                         cudaFuncAttributeMaxDynamicSharedMemorySize, smem_bytes);
    (void)attr_done;

    build_table_kernel<<<V_, H_>>>(embed_W, ff_w1, ff_b1, ff_w2, ff_b2,
                                   ln_w, ln_b);
    build_gram_kernel<<<V_, H_>>>();
    scan_kernel<<<B_ / 2, 128, smem_bytes>>>(seq, read_w, read_b,
                                             out_w, out_b, out);
}